// round 2
// baseline (speedup 1.0000x reference)
#include <cuda_runtime.h>
#include <math.h>

#define NBINS 30
#define NCELLS (NBINS * NBINS)
#define NFEAT 32          // 16 u-columns + 16 s-columns
#define MMSLOTS 33        // y, u0..15, s0..15

__device__ unsigned int g_hist[NFEAT * NCELLS];
__device__ unsigned int g_min[MMSLOTS];
__device__ unsigned int g_max[MMSLOTS];
__device__ double g_sum_abs;

// monotone float <-> uint mapping for atomicMin/Max
__device__ __forceinline__ unsigned enc(float f) {
    unsigned u = __float_as_uint(f);
    return (u & 0x80000000u) ? ~u : (u | 0x80000000u);
}
__device__ __forceinline__ float dec(unsigned u) {
    unsigned v = (u & 0x80000000u) ? (u ^ 0x80000000u) : ~u;
    return __uint_as_float(v);
}

__device__ __forceinline__ int binf(float x, float m, float iv) {
    int b = (int)floorf((x - m) * iv);
    b = b < 0 ? 0 : b;
    return b > (NBINS - 1) ? (NBINS - 1) : b;
}

// ---------------------------------------------------------------- init
__global__ void k_init() {
    int i = blockIdx.x * blockDim.x + threadIdx.x;
    int stride = gridDim.x * blockDim.x;
    for (int j = i; j < NFEAT * NCELLS; j += stride) g_hist[j] = 0u;
    if (i < MMSLOTS) { g_min[i] = 0xFFFFFFFFu; g_max[i] = 0u; }
    if (i == 0) g_sum_abs = 0.0;
}

// ---------------------------------------------------------------- pass 1: min/max + L1
__global__ void __launch_bounds__(256) k_minmax(
    const float* __restrict__ yt, const float* __restrict__ yp,
    const float* __restrict__ u, const float* __restrict__ s, int N)
{
    float ymn = INFINITY, ymx = -INFINITY;
    float umn[16], umx[16], smn[16], smx[16];
#pragma unroll
    for (int f = 0; f < 16; f++) {
        umn[f] = INFINITY; umx[f] = -INFINITY;
        smn[f] = INFINITY; smx[f] = -INFINITY;
    }
    float sab = 0.0f;

    int stride = gridDim.x * blockDim.x;
    for (int i = blockIdx.x * blockDim.x + threadIdx.x; i < N; i += stride) {
        float a = yt[i], b = yp[i];
        sab += fabsf(a - b);
        ymn = fminf(ymn, b); ymx = fmaxf(ymx, b);
        const float4* ur = reinterpret_cast<const float4*>(u) + (size_t)i * 4;
        const float4* sr = reinterpret_cast<const float4*>(s) + (size_t)i * 4;
#pragma unroll
        for (int q = 0; q < 4; q++) {
            float4 uv = ur[q];
            float4 sv = sr[q];
            umn[4*q+0] = fminf(umn[4*q+0], uv.x); umx[4*q+0] = fmaxf(umx[4*q+0], uv.x);
            umn[4*q+1] = fminf(umn[4*q+1], uv.y); umx[4*q+1] = fmaxf(umx[4*q+1], uv.y);
            umn[4*q+2] = fminf(umn[4*q+2], uv.z); umx[4*q+2] = fmaxf(umx[4*q+2], uv.z);
            umn[4*q+3] = fminf(umn[4*q+3], uv.w); umx[4*q+3] = fmaxf(umx[4*q+3], uv.w);
            smn[4*q+0] = fminf(smn[4*q+0], sv.x); smx[4*q+0] = fmaxf(smx[4*q+0], sv.x);
            smn[4*q+1] = fminf(smn[4*q+1], sv.y); smx[4*q+1] = fmaxf(smx[4*q+1], sv.y);
            smn[4*q+2] = fminf(smn[4*q+2], sv.z); smx[4*q+2] = fmaxf(smx[4*q+2], sv.z);
            smn[4*q+3] = fminf(smn[4*q+3], sv.w); smx[4*q+3] = fmaxf(smx[4*q+3], sv.w);
        }
    }

    // gather into one indexed array: [0..32]=mins(y,u,s) [33..65]=maxes [66]=sum
    float all[67];
    all[0] = ymn; all[33] = ymx;
#pragma unroll
    for (int f = 0; f < 16; f++) {
        all[1 + f]  = umn[f]; all[17 + f] = smn[f];
        all[34 + f] = umx[f]; all[50 + f] = smx[f];
    }
    all[66] = sab;

    __shared__ float red[67 * 8];
    int wid = threadIdx.x >> 5, lane = threadIdx.x & 31;
#pragma unroll
    for (int q = 0; q < 67; q++) {
        float v = all[q];
#pragma unroll
        for (int o = 16; o; o >>= 1) {
            float other = __shfl_xor_sync(0xffffffffu, v, o);
            v = (q < 33) ? fminf(v, other) : (q < 66 ? fmaxf(v, other) : v + other);
        }
        if (lane == 0) red[q * 8 + wid] = v;
    }
    __syncthreads();
    if (threadIdx.x < 67) {
        int q = threadIdx.x;
        float v = red[q * 8];
        for (int w = 1; w < 8; w++) {
            float o = red[q * 8 + w];
            v = (q < 33) ? fminf(v, o) : (q < 66 ? fmaxf(v, o) : v + o);
        }
        if (q < 33)       atomicMin(&g_min[q], enc(v));
        else if (q < 66)  atomicMax(&g_max[q - 33], enc(v));
        else              atomicAdd(&g_sum_abs, (double)v);
    }
}

// ---------------------------------------------------------------- pass 2: histograms
__global__ void __launch_bounds__(1024) k_hist(
    const float* __restrict__ yp, const float* __restrict__ u,
    const float* __restrict__ s, int N)
{
    extern __shared__ unsigned int sh[];   // NFEAT * NCELLS counters
    __shared__ float smn[MMSLOTS], sinv[MMSLOTS];
    int tid = threadIdx.x;
    if (tid < MMSLOTS) {
        float lo = dec(g_min[tid]);
        float hi = dec(g_max[tid]);
        smn[tid]  = lo;
        sinv[tid] = (float)NBINS / (hi - lo);
    }
    for (int j = tid; j < NFEAT * NCELLS; j += blockDim.x) sh[j] = 0u;
    __syncthreads();

    int stride = gridDim.x * blockDim.x;
    for (int i = blockIdx.x * blockDim.x + tid; i < N; i += stride) {
        float y = yp[i];
        int iy = binf(y, smn[0], sinv[0]);
        const float4* ur = reinterpret_cast<const float4*>(u) + (size_t)i * 4;
        const float4* sr = reinterpret_cast<const float4*>(s) + (size_t)i * 4;
#pragma unroll
        for (int q = 0; q < 4; q++) {
            float4 uv = ur[q];
            float4 sv = sr[q];
            float uu[4] = {uv.x, uv.y, uv.z, uv.w};
            float ss[4] = {sv.x, sv.y, sv.z, sv.w};
#pragma unroll
            for (int k = 0; k < 4; k++) {
                int f = 4 * q + k;
                int ixu = binf(uu[k], smn[1 + f],  sinv[1 + f]);
                atomicAdd(&sh[f * NCELLS + ixu * NBINS + iy], 1u);
                int ixs = binf(ss[k], smn[17 + f], sinv[17 + f]);
                atomicAdd(&sh[(16 + f) * NCELLS + ixs * NBINS + iy], 1u);
            }
        }
    }
    __syncthreads();
    for (int j = tid; j < NFEAT * NCELLS; j += blockDim.x) {
        unsigned v = sh[j];
        if (v) atomicAdd(&g_hist[j], v);
    }
}

// ---------------------------------------------------------------- mi_us (16x16 rows)
__device__ double mi_us_row(const float* __restrict__ u, const float* __restrict__ s) {
    float uv[16], sv[16];
#pragma unroll
    for (int j = 0; j < 16; j++) { uv[j] = u[j]; sv[j] = s[j]; }
    float umn = uv[0], umx = uv[0], sm = sv[0], sx = sv[0];
#pragma unroll
    for (int j = 1; j < 16; j++) {
        umn = fminf(umn, uv[j]); umx = fmaxf(umx, uv[j]);
        sm  = fminf(sm,  sv[j]); sx  = fmaxf(sx,  sv[j]);
    }
    // linspace(min, max, 30): step = (max-min)/29, edges = min + i*step, last forced = max
    float ustep = (umx - umn) / 29.0f;
    float sstep = (sx - sm) / 29.0f;
    int lu[16], ls[16];
#pragma unroll
    for (int k = 0; k < 16; k++) {
        int cu = 0, cs = 0;
        for (int j = 0; j < 30; j++) {
            float eu = (j == 29) ? umx : __fadd_rn(umn, __fmul_rn((float)j, ustep));
            float es = (j == 29) ? sx  : __fadd_rn(sm,  __fmul_rn((float)j, sstep));
            cu += (eu <= uv[k]);
            cs += (es <= sv[k]);
        }
        lu[k] = cu; ls[k] = cs;
    }
    // sklearn mutual_info_score over 16 labeled samples (natural log, skip zero cells)
    double mi = 0.0;
    for (int k = 0; k < 16; k++) {
        bool first = true;
        for (int m = 0; m < k; m++)
            if (lu[m] == lu[k] && ls[m] == ls[k]) { first = false; break; }
        if (!first) continue;
        int C = 0, A = 0, B = 0;
        for (int m = 0; m < 16; m++) {
            int eq_u = (lu[m] == lu[k]);
            int eq_s = (ls[m] == ls[k]);
            C += eq_u & eq_s;
            A += eq_u;
            B += eq_s;
        }
        mi += ((double)C / 16.0) * log(((double)C * 16.0) / ((double)A * (double)B));
    }
    return mi;
}

// ---------------------------------------------------------------- pass 3: MI + combine
__global__ void __launch_bounds__(1024) k_final(
    const float* __restrict__ u, const float* __restrict__ s,
    float* __restrict__ out, int N, int out_size)
{
    __shared__ double terms[64];
    __shared__ float As[32][NBINS], Bs[32][NBINS];
    int tid = threadIdx.x, w = tid >> 5, lane = tid & 31;

    // each warp computes MI for one (feature, y) histogram pair
    {
        const unsigned* h = &g_hist[w * NCELLS];
        if (lane < NBINS) {
            float ra = 0.0f, rb = 0.0f;
            for (int j = 0; j < NBINS; j++) {
                ra += (float)h[lane * NBINS + j];
                rb += (float)h[j * NBINS + lane];
            }
            As[w][lane] = ra;
            Bs[w][lane] = rb;
        }
        __syncwarp();
        double tot = (double)N;
        double mi = 0.0;
        for (int c = lane; c < NCELLS; c += 32) {
            int i = c / NBINS, j = c % NBINS;
            double px = (double)As[w][i] / tot; if (px == 0.0) px = 1e-10;
            double py = (double)Bs[w][j] / tot; if (py == 0.0) py = 1e-10;
            unsigned cc = h[c];
            double pxy = cc ? (double)cc / tot : 1e-10;
            mi += pxy * (double)logf((float)(pxy / (px * py)));
        }
#pragma unroll
        for (int o = 16; o; o >>= 1) mi += __shfl_xor_sync(0xffffffffu, mi, o);
        if (lane == 0) terms[w] = 0.1 * mi;
    }
    __syncthreads();

    if (tid < 16) {
        terms[32 + tid] = -0.05 * mi_us_row(u + tid * 16, s + tid * 16);  // 0.1 * 0.5
    } else if (tid == 16) {
        terms[48] = g_sum_abs / (double)N;   // L_PT
    } else if (tid < 32) {
        terms[32 + tid] = 0.0;               // slots 49..63
    }
    __syncthreads();

    // zero the tail of out first (poisoned by harness), then write the scalar
    for (int k = tid + 1; k < out_size; k += blockDim.x) out[k] = 0.0f;
    __syncthreads();

    if (tid == 0) {
        double acc = 0.0;
        for (int k = 0; k < 64; k++) acc += terms[k];
        out[0] = (float)acc;
    }
}

// ---------------------------------------------------------------- launch
extern "C" void kernel_launch(void* const* d_in, const int* in_sizes, int n_in,
                              void* d_out, int out_size) {
    const float* y_true = (const float*)d_in[0];
    const float* y_pred = (const float*)d_in[1];
    // d_in[2] = u_attr, d_in[3] = s_attr  (unused by the reference)
    const float* u_vec  = (const float*)d_in[4];
    const float* s_vec  = (const float*)d_in[5];
    int N = in_sizes[0];

    k_init<<<32, 256>>>();
    k_minmax<<<592, 256>>>(y_true, y_pred, u_vec, s_vec, N);

    size_t shbytes = (size_t)NFEAT * NCELLS * sizeof(unsigned);
    cudaFuncSetAttribute(k_hist, cudaFuncAttributeMaxDynamicSharedMemorySize, (int)shbytes);
    k_hist<<<148, 1024, shbytes>>>(y_pred, u_vec, s_vec, N);

    k_final<<<1, 1024>>>(u_vec, s_vec, (float*)d_out, N, out_size);
}

// round 3
// speedup vs baseline: 3.4527x; 3.4527x over previous
#include <cuda_runtime.h>
#include <math.h>

#define NBINS 30
#define NCELLS (NBINS * NBINS)
#define NFEAT 32          // 16 u-columns + 16 s-columns
#define MMSLOTS 33        // y, u0..15, s0..15

__device__ unsigned int g_hist[NFEAT * NCELLS];
__device__ unsigned int g_min[MMSLOTS];
__device__ unsigned int g_max[MMSLOTS];
__device__ double g_sum_abs;

// monotone float <-> uint mapping for atomicMin/Max
__device__ __forceinline__ unsigned enc(float f) {
    unsigned u = __float_as_uint(f);
    return (u & 0x80000000u) ? ~u : (u | 0x80000000u);
}
__device__ __forceinline__ float dec(unsigned u) {
    unsigned v = (u & 0x80000000u) ? (u ^ 0x80000000u) : ~u;
    return __uint_as_float(v);
}

__device__ __forceinline__ int binf(float x, float m, float iv) {
    int b = (int)floorf((x - m) * iv);
    b = b < 0 ? 0 : b;
    return b > (NBINS - 1) ? (NBINS - 1) : b;
}

// ---------------------------------------------------------------- init
__global__ void k_init() {
    int i = blockIdx.x * blockDim.x + threadIdx.x;
    int stride = gridDim.x * blockDim.x;
    for (int j = i; j < NFEAT * NCELLS; j += stride) g_hist[j] = 0u;
    if (i < MMSLOTS) { g_min[i] = 0xFFFFFFFFu; g_max[i] = 0u; }
    if (i == 0) g_sum_abs = 0.0;
}

// ---------------------------------------------------------------- pass 1: min/max + L1
__global__ void __launch_bounds__(256) k_minmax(
    const float* __restrict__ yt, const float* __restrict__ yp,
    const float* __restrict__ u, const float* __restrict__ s, int N)
{
    float ymn = INFINITY, ymx = -INFINITY;
    float umn[16], umx[16], smn[16], smx[16];
#pragma unroll
    for (int f = 0; f < 16; f++) {
        umn[f] = INFINITY; umx[f] = -INFINITY;
        smn[f] = INFINITY; smx[f] = -INFINITY;
    }
    float sab = 0.0f;

    int stride = gridDim.x * blockDim.x;
    for (int i = blockIdx.x * blockDim.x + threadIdx.x; i < N; i += stride) {
        float a = yt[i], b = yp[i];
        sab += fabsf(a - b);
        ymn = fminf(ymn, b); ymx = fmaxf(ymx, b);
        const float4* ur = reinterpret_cast<const float4*>(u) + (size_t)i * 4;
        const float4* sr = reinterpret_cast<const float4*>(s) + (size_t)i * 4;
#pragma unroll
        for (int q = 0; q < 4; q++) {
            float4 uv = ur[q];
            float4 sv = sr[q];
            umn[4*q+0] = fminf(umn[4*q+0], uv.x); umx[4*q+0] = fmaxf(umx[4*q+0], uv.x);
            umn[4*q+1] = fminf(umn[4*q+1], uv.y); umx[4*q+1] = fmaxf(umx[4*q+1], uv.y);
            umn[4*q+2] = fminf(umn[4*q+2], uv.z); umx[4*q+2] = fmaxf(umx[4*q+2], uv.z);
            umn[4*q+3] = fminf(umn[4*q+3], uv.w); umx[4*q+3] = fmaxf(umx[4*q+3], uv.w);
            smn[4*q+0] = fminf(smn[4*q+0], sv.x); smx[4*q+0] = fmaxf(smx[4*q+0], sv.x);
            smn[4*q+1] = fminf(smn[4*q+1], sv.y); smx[4*q+1] = fmaxf(smx[4*q+1], sv.y);
            smn[4*q+2] = fminf(smn[4*q+2], sv.z); smx[4*q+2] = fmaxf(smx[4*q+2], sv.z);
            smn[4*q+3] = fminf(smn[4*q+3], sv.w); smx[4*q+3] = fmaxf(smx[4*q+3], sv.w);
        }
    }

    // gather into one indexed array: [0..32]=mins(y,u,s) [33..65]=maxes [66]=sum
    float all[67];
    all[0] = ymn; all[33] = ymx;
#pragma unroll
    for (int f = 0; f < 16; f++) {
        all[1 + f]  = umn[f]; all[17 + f] = smn[f];
        all[34 + f] = umx[f]; all[50 + f] = smx[f];
    }
    all[66] = sab;

    __shared__ float red[67 * 8];
    int wid = threadIdx.x >> 5, lane = threadIdx.x & 31;
#pragma unroll
    for (int q = 0; q < 67; q++) {
        float v = all[q];
#pragma unroll
        for (int o = 16; o; o >>= 1) {
            float other = __shfl_xor_sync(0xffffffffu, v, o);
            v = (q < 33) ? fminf(v, other) : (q < 66 ? fmaxf(v, other) : v + other);
        }
        if (lane == 0) red[q * 8 + wid] = v;
    }
    __syncthreads();
    if (threadIdx.x < 67) {
        int q = threadIdx.x;
        float v = red[q * 8];
        for (int w = 1; w < 8; w++) {
            float o = red[q * 8 + w];
            v = (q < 33) ? fminf(v, o) : (q < 66 ? fmaxf(v, o) : v + o);
        }
        if (q < 33)       atomicMin(&g_min[q], enc(v));
        else if (q < 66)  atomicMax(&g_max[q - 33], enc(v));
        else              atomicAdd(&g_sum_abs, (double)v);
    }
}

// ---------------------------------------------------------------- pass 2: histograms
__global__ void __launch_bounds__(1024) k_hist(
    const float* __restrict__ yp, const float* __restrict__ u,
    const float* __restrict__ s, int N)
{
    extern __shared__ unsigned int sh[];   // NFEAT * NCELLS counters
    __shared__ float smn[MMSLOTS], sinv[MMSLOTS];
    int tid = threadIdx.x;
    if (tid < MMSLOTS) {
        float lo = dec(g_min[tid]);
        float hi = dec(g_max[tid]);
        smn[tid]  = lo;
        sinv[tid] = (float)NBINS / (hi - lo);
    }
    for (int j = tid; j < NFEAT * NCELLS; j += blockDim.x) sh[j] = 0u;
    __syncthreads();

    int stride = gridDim.x * blockDim.x;
    for (int i = blockIdx.x * blockDim.x + tid; i < N; i += stride) {
        float y = yp[i];
        int iy = binf(y, smn[0], sinv[0]);
        const float4* ur = reinterpret_cast<const float4*>(u) + (size_t)i * 4;
        const float4* sr = reinterpret_cast<const float4*>(s) + (size_t)i * 4;
#pragma unroll
        for (int q = 0; q < 4; q++) {
            float4 uv = ur[q];
            float4 sv = sr[q];
            float uu[4] = {uv.x, uv.y, uv.z, uv.w};
            float ss[4] = {sv.x, sv.y, sv.z, sv.w};
#pragma unroll
            for (int k = 0; k < 4; k++) {
                int f = 4 * q + k;
                int ixu = binf(uu[k], smn[1 + f],  sinv[1 + f]);
                atomicAdd(&sh[f * NCELLS + ixu * NBINS + iy], 1u);
                int ixs = binf(ss[k], smn[17 + f], sinv[17 + f]);
                atomicAdd(&sh[(16 + f) * NCELLS + ixs * NBINS + iy], 1u);
            }
        }
    }
    __syncthreads();
    for (int j = tid; j < NFEAT * NCELLS; j += blockDim.x) {
        unsigned v = sh[j];
        if (v) atomicAdd(&g_hist[j], v);
    }
}

// ---------------------------------------------------------------- mi_us (16x16 rows), all fp32
__device__ float mi_us_row(const float* __restrict__ u, const float* __restrict__ s) {
    float uv[16], sv[16];
#pragma unroll
    for (int j = 0; j < 16; j++) { uv[j] = u[j]; sv[j] = s[j]; }
    float umn = uv[0], umx = uv[0], sm = sv[0], sx = sv[0];
#pragma unroll
    for (int j = 1; j < 16; j++) {
        umn = fminf(umn, uv[j]); umx = fmaxf(umx, uv[j]);
        sm  = fminf(sm,  sv[j]); sx  = fmaxf(sx,  sv[j]);
    }
    // linspace(min, max, 30): step = (max-min)/29, edges = min + i*step, last forced = max
    float ustep = (umx - umn) / 29.0f;
    float sstep = (sx - sm) / 29.0f;
    int lu[16], ls[16];
#pragma unroll
    for (int k = 0; k < 16; k++) {
        int cu = 0, cs = 0;
        for (int j = 0; j < 30; j++) {
            float eu = (j == 29) ? umx : __fadd_rn(umn, __fmul_rn((float)j, ustep));
            float es = (j == 29) ? sx  : __fadd_rn(sm,  __fmul_rn((float)j, sstep));
            cu += (eu <= uv[k]);
            cs += (es <= sv[k]);
        }
        lu[k] = cu; ls[k] = cs;
    }
    // sklearn mutual_info_score over 16 labeled samples (natural log, skip zero cells)
    float mi = 0.0f;
    for (int k = 0; k < 16; k++) {
        bool first = true;
        for (int m = 0; m < k; m++)
            if (lu[m] == lu[k] && ls[m] == ls[k]) { first = false; break; }
        if (!first) continue;
        int C = 0, A = 0, B = 0;
        for (int m = 0; m < 16; m++) {
            int eq_u = (lu[m] == lu[k]);
            int eq_s = (ls[m] == ls[k]);
            C += eq_u & eq_s;
            A += eq_u;
            B += eq_s;
        }
        mi += ((float)C * (1.0f / 16.0f)) * __logf(((float)(C * 16)) / ((float)(A * B)));
    }
    return mi;
}

// ---------------------------------------------------------------- pass 3: MI + combine (fp32 hot path)
__global__ void __launch_bounds__(1024) k_final(
    const float* __restrict__ u, const float* __restrict__ s,
    float* __restrict__ out, int N, int out_size)
{
    __shared__ double terms[64];
    __shared__ float As[32][NBINS], Bs[32][NBINS];
    int tid = threadIdx.x, w = tid >> 5, lane = tid & 31;

    // each warp computes MI for one (feature, y) histogram pair
    {
        const unsigned* h = &g_hist[w * NCELLS];
        if (lane < NBINS) {
            float ra = 0.0f, rb = 0.0f;
            for (int j = 0; j < NBINS; j++) {
                ra += (float)h[lane * NBINS + j];
                rb += (float)h[j * NBINS + lane];
            }
            As[w][lane] = ra;
            Bs[w][lane] = rb;
        }
        __syncwarp();
        float invTot = 1.0f / (float)N;
        float mi = 0.0f;
        for (int c = lane; c < NCELLS; c += 32) {
            int i = c / NBINS, j = c % NBINS;
            float px = As[w][i] * invTot; if (px == 0.0f) px = 1e-10f;
            float py = Bs[w][j] * invTot; if (py == 0.0f) py = 1e-10f;
            unsigned cc = h[c];
            float pxy = cc ? (float)cc * invTot : 1e-10f;
            mi += pxy * __logf(pxy / (px * py));
        }
#pragma unroll
        for (int o = 16; o; o >>= 1) mi += __shfl_xor_sync(0xffffffffu, mi, o);
        if (lane == 0) terms[w] = 0.1 * (double)mi;
    }
    __syncthreads();

    if (tid < 16) {
        terms[32 + tid] = -0.05 * (double)mi_us_row(u + tid * 16, s + tid * 16);  // 0.1 * 0.5
    } else if (tid == 16) {
        terms[48] = g_sum_abs / (double)N;   // L_PT
    } else if (tid < 32) {
        terms[32 + tid] = 0.0;               // slots 49..63
    }
    __syncthreads();

    // zero the tail of out first (poisoned by harness), then write the scalar
    for (int k = tid + 1; k < out_size; k += blockDim.x) out[k] = 0.0f;
    __syncthreads();

    if (tid == 0) {
        double acc = 0.0;
        for (int k = 0; k < 64; k++) acc += terms[k];
        out[0] = (float)acc;
    }
}

// ---------------------------------------------------------------- launch
extern "C" void kernel_launch(void* const* d_in, const int* in_sizes, int n_in,
                              void* d_out, int out_size) {
    const float* y_true = (const float*)d_in[0];
    const float* y_pred = (const float*)d_in[1];
    // d_in[2] = u_attr, d_in[3] = s_attr  (unused by the reference)
    const float* u_vec  = (const float*)d_in[4];
    const float* s_vec  = (const float*)d_in[5];
    int N = in_sizes[0];

    k_init<<<32, 256>>>();
    k_minmax<<<592, 256>>>(y_true, y_pred, u_vec, s_vec, N);

    size_t shbytes = (size_t)NFEAT * NCELLS * sizeof(unsigned);
    cudaFuncSetAttribute(k_hist, cudaFuncAttributeMaxDynamicSharedMemorySize, (int)shbytes);
    k_hist<<<148, 1024, shbytes>>>(y_pred, u_vec, s_vec, N);

    k_final<<<1, 1024>>>(u_vec, s_vec, (float*)d_out, N, out_size);
}

// round 6
// speedup vs baseline: 4.8537x; 1.4058x over previous
#include <cuda_runtime.h>
#include <math.h>

#define NBINS 30
#define NCELLS (NBINS * NBINS)
#define NFEAT 32          // 16 u-columns + 16 s-columns
#define MMSLOTS 33        // y, u0..15, s0..15

__device__ unsigned int g_hist[NFEAT * NCELLS];
__device__ unsigned int g_min[MMSLOTS];
__device__ unsigned int g_max[MMSLOTS];
__device__ double g_sum_abs;
__device__ double g_mius[16];

// monotone float <-> uint mapping for atomicMin/Max
__device__ __forceinline__ unsigned enc(float f) {
    unsigned u = __float_as_uint(f);
    return (u & 0x80000000u) ? ~u : (u | 0x80000000u);
}
__device__ __forceinline__ float dec(unsigned u) {
    unsigned v = (u & 0x80000000u) ? (u ^ 0x80000000u) : ~u;
    return __uint_as_float(v);
}

__device__ __forceinline__ int binf(float x, float m, float iv) {
    int b = (int)floorf((x - m) * iv);
    b = b < 0 ? 0 : b;
    return b > (NBINS - 1) ? (NBINS - 1) : b;
}

// ---------------------------------------------------------------- init + mi_us
// Blocks 0..15: warp 0 computes mi_us for row r = blockIdx.x (16 lanes cooperate).
// All blocks also help zero g_hist.
__global__ void k_init(const float* __restrict__ u, const float* __restrict__ s) {
    int i = blockIdx.x * blockDim.x + threadIdx.x;
    int stride = gridDim.x * blockDim.x;
    for (int j = i; j < NFEAT * NCELLS; j += stride) g_hist[j] = 0u;
    if (i == 0) g_sum_abs = 0.0;
    if (i < MMSLOTS) { g_min[i] = 0xFFFFFFFFu; g_max[i] = 0u; }

    if (blockIdx.x < 16 && threadIdx.x < 32) {
        int r = blockIdx.x;
        int lane = threadIdx.x;
        int k = lane & 15;                 // sample index 0..15 (lanes 16..31 mirror)
        float uk = u[r * 16 + k];
        float sk = s[r * 16 + k];
        // min/max over 16 samples via shfl (lanes 16..31 hold copies; harmless)
        float umn = uk, umx = uk, smn2 = sk, smx2 = sk;
#pragma unroll
        for (int o = 8; o; o >>= 1) {
            umn  = fminf(umn,  __shfl_xor_sync(0xffffffffu, umn,  o));
            umx  = fmaxf(umx,  __shfl_xor_sync(0xffffffffu, umx,  o));
            smn2 = fminf(smn2, __shfl_xor_sync(0xffffffffu, smn2, o));
            smx2 = fmaxf(smx2, __shfl_xor_sync(0xffffffffu, smx2, o));
        }
        float ustep = (umx - umn) / 29.0f;
        float sstep = (smx2 - smn2) / 29.0f;
        // labels: np.digitize == count of edges <= v, edges = min + j*step (last forced to max)
        int cu = 0, cs = 0;
#pragma unroll
        for (int j = 0; j < 30; j++) {
            float eu = (j == 29) ? umx  : __fadd_rn(umn,  __fmul_rn((float)j, ustep));
            float es = (j == 29) ? smx2 : __fadd_rn(smn2, __fmul_rn((float)j, sstep));
            cu += (eu <= uk);
            cs += (es <= sk);
        }
        // gather all 16 label pairs via shfl
        int lus[16], lss[16];
#pragma unroll
        for (int m = 0; m < 16; m++) {
            lus[m] = __shfl_sync(0xffffffffu, cu, m);
            lss[m] = __shfl_sync(0xffffffffu, cs, m);
        }
        float mi = 0.0f;
        if (lane < 16) {
            // first-occurrence check for this lane's (cu,cs) cell
            bool first = true;
            for (int m = 0; m < k; m++)
                if (lus[m] == cu && lss[m] == cs) { first = false; break; }
            if (first) {
                int C = 0, A = 0, B = 0;
#pragma unroll
                for (int m = 0; m < 16; m++) {
                    int eq_u = (lus[m] == cu);
                    int eq_s = (lss[m] == cs);
                    C += eq_u & eq_s;
                    A += eq_u;
                    B += eq_s;
                }
                mi = ((float)C * (1.0f / 16.0f)) * __logf(((float)(C * 16)) / ((float)(A * B)));
            }
        }
#pragma unroll
        for (int o = 8; o; o >>= 1) mi += __shfl_xor_sync(0x0000ffffu, mi, o);
        if (lane == 0) g_mius[r] = (double)mi;
    }
}

// ---------------------------------------------------------------- pass 1: min/max + L1
__global__ void __launch_bounds__(256) k_minmax(
    const float* __restrict__ yt, const float* __restrict__ yp,
    const float* __restrict__ u, const float* __restrict__ s, int N)
{
    float ymn = INFINITY, ymx = -INFINITY;
    float umn[16], umx[16], smn[16], smx[16];
#pragma unroll
    for (int f = 0; f < 16; f++) {
        umn[f] = INFINITY; umx[f] = -INFINITY;
        smn[f] = INFINITY; smx[f] = -INFINITY;
    }
    float sab = 0.0f;

    int stride = gridDim.x * blockDim.x;
    for (int i = blockIdx.x * blockDim.x + threadIdx.x; i < N; i += stride) {
        float a = yt[i], b = yp[i];
        sab += fabsf(a - b);
        ymn = fminf(ymn, b); ymx = fmaxf(ymx, b);
        const float4* ur = reinterpret_cast<const float4*>(u) + (size_t)i * 4;
        const float4* sr = reinterpret_cast<const float4*>(s) + (size_t)i * 4;
#pragma unroll
        for (int q = 0; q < 4; q++) {
            float4 uv = ur[q];
            float4 sv = sr[q];
            umn[4*q+0] = fminf(umn[4*q+0], uv.x); umx[4*q+0] = fmaxf(umx[4*q+0], uv.x);
            umn[4*q+1] = fminf(umn[4*q+1], uv.y); umx[4*q+1] = fmaxf(umx[4*q+1], uv.y);
            umn[4*q+2] = fminf(umn[4*q+2], uv.z); umx[4*q+2] = fmaxf(umx[4*q+2], uv.z);
            umn[4*q+3] = fminf(umn[4*q+3], uv.w); umx[4*q+3] = fmaxf(umx[4*q+3], uv.w);
            smn[4*q+0] = fminf(smn[4*q+0], sv.x); smx[4*q+0] = fmaxf(smx[4*q+0], sv.x);
            smn[4*q+1] = fminf(smn[4*q+1], sv.y); smx[4*q+1] = fmaxf(smx[4*q+1], sv.y);
            smn[4*q+2] = fminf(smn[4*q+2], sv.z); smx[4*q+2] = fmaxf(smx[4*q+2], sv.z);
            smn[4*q+3] = fminf(smn[4*q+3], sv.w); smx[4*q+3] = fmaxf(smx[4*q+3], sv.w);
        }
    }

    // gather into one indexed array: [0..32]=mins(y,u,s) [33..65]=maxes [66]=sum
    float all[67];
    all[0] = ymn; all[33] = ymx;
#pragma unroll
    for (int f = 0; f < 16; f++) {
        all[1 + f]  = umn[f]; all[17 + f] = smn[f];
        all[34 + f] = umx[f]; all[50 + f] = smx[f];
    }
    all[66] = sab;

    __shared__ float red[67 * 8];
    int wid = threadIdx.x >> 5, lane = threadIdx.x & 31;
#pragma unroll
    for (int q = 0; q < 67; q++) {
        float v = all[q];
#pragma unroll
        for (int o = 16; o; o >>= 1) {
            float other = __shfl_xor_sync(0xffffffffu, v, o);
            v = (q < 33) ? fminf(v, other) : (q < 66 ? fmaxf(v, other) : v + other);
        }
        if (lane == 0) red[q * 8 + wid] = v;
    }
    __syncthreads();
    if (threadIdx.x < 67) {
        int q = threadIdx.x;
        float v = red[q * 8];
        for (int w = 1; w < 8; w++) {
            float o = red[q * 8 + w];
            v = (q < 33) ? fminf(v, o) : (q < 66 ? fmaxf(v, o) : v + o);
        }
        if (q < 33)       atomicMin(&g_min[q], enc(v));
        else if (q < 66)  atomicMax(&g_max[q - 33], enc(v));
        else              atomicAdd(&g_sum_abs, (double)v);
    }
}

// ---------------------------------------------------------------- pass 2: histograms
// Even CTAs handle the 16 u-features; odd CTAs the 16 s-features.
// 57.6 KB smem each -> 2 CTAs / SM.
__global__ void __launch_bounds__(1024, 2) k_hist(
    const float* __restrict__ yp, const float* __restrict__ u,
    const float* __restrict__ s, int N)
{
    extern __shared__ unsigned int sh[];   // 16 * NCELLS counters
    __shared__ float smn[MMSLOTS], sinv[MMSLOTS];
    int tid = threadIdx.x;
    if (tid < MMSLOTS) {
        float lo = dec(g_min[tid]);
        float hi = dec(g_max[tid]);
        smn[tid]  = lo;
        sinv[tid] = (float)NBINS / (hi - lo);
    }
    for (int j = tid; j < 16 * NCELLS; j += blockDim.x) sh[j] = 0u;
    __syncthreads();

    int half = blockIdx.x & 1;                    // 0 -> u features, 1 -> s features
    const float* base = half ? s : u;
    int mmoff = half ? 17 : 1;

    int nb = gridDim.x >> 1;
    int stride = nb * blockDim.x;
    for (int i = (blockIdx.x >> 1) * blockDim.x + tid; i < N; i += stride) {
        float y = yp[i];
        int iy = binf(y, smn[0], sinv[0]);
        const float4* vr = reinterpret_cast<const float4*>(base) + (size_t)i * 4;
#pragma unroll
        for (int q = 0; q < 4; q++) {
            float4 v = vr[q];
            float vv[4] = {v.x, v.y, v.z, v.w};
#pragma unroll
            for (int k = 0; k < 4; k++) {
                int f = 4 * q + k;
                int ix = binf(vv[k], smn[mmoff + f], sinv[mmoff + f]);
                atomicAdd(&sh[f * NCELLS + ix * NBINS + iy], 1u);
            }
        }
    }
    __syncthreads();
    unsigned int* gh = g_hist + half * 16 * NCELLS;
    for (int j = tid; j < 16 * NCELLS; j += blockDim.x) {
        unsigned v = sh[j];
        if (v) atomicAdd(&gh[j], v);
    }
}

// ---------------------------------------------------------------- pass 3: MI + combine
// One CTA. Stage the full histogram into shared, then each warp does one feature.
__global__ void __launch_bounds__(1024) k_final(
    float* __restrict__ out, int N, int out_size)
{
    extern __shared__ unsigned int hsh[];       // NFEAT * NCELLS
    __shared__ double terms[64];
    __shared__ float As[32][NBINS], Bs[32][NBINS];
    int tid = threadIdx.x, w = tid >> 5, lane = tid & 31;

    // bulk coalesced load of histograms
    for (int j = tid; j < NFEAT * NCELLS; j += blockDim.x) hsh[j] = g_hist[j];
    __syncthreads();

    {
        const unsigned* h = &hsh[w * NCELLS];
        if (lane < NBINS) {
            float ra = 0.0f, rb = 0.0f;
#pragma unroll
            for (int j = 0; j < NBINS; j++) {
                ra += (float)h[lane * NBINS + j];
                rb += (float)h[j * NBINS + lane];
            }
            As[w][lane] = ra;
            Bs[w][lane] = rb;
        }
        __syncwarp();
        float invTot = 1.0f / (float)N;
        float mi = 0.0f;
        for (int c = lane; c < NCELLS; c += 32) {
            int i = c / NBINS, j = c - i * NBINS;
            float px = As[w][i] * invTot; if (px == 0.0f) px = 1e-10f;
            float py = Bs[w][j] * invTot; if (py == 0.0f) py = 1e-10f;
            unsigned cc = h[c];
            float pxy = cc ? (float)cc * invTot : 1e-10f;
            mi += pxy * __logf(pxy / (px * py));
        }
#pragma unroll
        for (int o = 16; o; o >>= 1) mi += __shfl_xor_sync(0xffffffffu, mi, o);
        if (lane == 0) terms[w] = 0.1 * (double)mi;
    }
    __syncthreads();

    if (tid < 16) {
        terms[32 + tid] = -0.05 * g_mius[tid];    // 0.1 * 0.5 * mi_us
    } else if (tid == 16) {
        terms[48] = g_sum_abs / (double)N;        // L_PT
    } else if (tid < 32) {
        terms[32 + tid] = 0.0;
    }
    __syncthreads();

    for (int k = tid + 1; k < out_size; k += blockDim.x) out[k] = 0.0f;
    __syncthreads();

    if (tid == 0) {
        double acc = 0.0;
        for (int k = 0; k < 64; k++) acc += terms[k];
        out[0] = (float)acc;
    }
}

// ---------------------------------------------------------------- launch
extern "C" void kernel_launch(void* const* d_in, const int* in_sizes, int n_in,
                              void* d_out, int out_size) {
    const float* y_true = (const float*)d_in[0];
    const float* y_pred = (const float*)d_in[1];
    // d_in[2] = u_attr, d_in[3] = s_attr  (unused by the reference)
    const float* u_vec  = (const float*)d_in[4];
    const float* s_vec  = (const float*)d_in[5];
    int N = in_sizes[0];

    k_init<<<32, 256>>>(u_vec, s_vec);
    k_minmax<<<592, 256>>>(y_true, y_pred, u_vec, s_vec, N);

    size_t shbytes = (size_t)16 * NCELLS * sizeof(unsigned);          // 57.6 KB
    cudaFuncSetAttribute(k_hist, cudaFuncAttributeMaxDynamicSharedMemorySize, (int)shbytes);
    k_hist<<<296, 1024, shbytes>>>(y_pred, u_vec, s_vec, N);

    size_t fshbytes = (size_t)NFEAT * NCELLS * sizeof(unsigned);      // 115.2 KB
    cudaFuncSetAttribute(k_final, cudaFuncAttributeMaxDynamicSharedMemorySize, (int)fshbytes);
    k_final<<<1, 1024, fshbytes>>>((float*)d_out, N, out_size);
}